// round 6
// baseline (speedup 1.0000x reference)
#include <cuda_runtime.h>
#include <cfloat>

namespace {
constexpr int kB  = 2;
constexpr int kH  = 8;
constexpr int kS  = 2048;
constexpr int kDK = 32;
constexpr int kDM = 256;
constexpr int kNRow = kB * kS;           // 4096
constexpr float kScale = 0.17677669529663687f;  // 1/sqrt(32)
constexpr int kWarps   = 11;
constexpr int kThreads = kWarps * 32;    // 352
constexpr int kQPerCta = kWarps * 2;     // 22
constexpr int kCap     = 64;             // candidate cap per query
}

// Scratch: projected Q/K/V in [b,h,s,d] layout (4 MB each).
__device__ float g_q[kB * kH * kS * kDK];
__device__ float g_k[kB * kH * kS * kDK];
__device__ float g_v[kB * kH * kS * kDK];

// ---------------------------------------------------------------------------
// Projection GEMM (unchanged): out = X @ W^T + bias -> [b,h,s,d]
// ---------------------------------------------------------------------------
__global__ __launch_bounds__(256)
void proj_kernel(const float* __restrict__ xq, const float* __restrict__ xk,
                 const float* __restrict__ xv,
                 const float* __restrict__ wq, const float* __restrict__ bq,
                 const float* __restrict__ wk, const float* __restrict__ bk,
                 const float* __restrict__ wv, const float* __restrict__ bv)
{
    constexpr int PBM = 128, PBN = 64, PBK = 16;
    __shared__ float As[PBK][PBM];
    __shared__ float Bs[PBK][PBN];

    const int z = blockIdx.z;
    const float* __restrict__ X    = (z == 0) ? xq : (z == 1) ? xk : xv;
    const float* __restrict__ W    = (z == 0) ? wq : (z == 1) ? wk : wv;
    const float* __restrict__ bias = (z == 0) ? bq : (z == 1) ? bk : bv;
    float* __restrict__ out        = (z == 0) ? g_q : (z == 1) ? g_k : g_v;

    const int n0 = blockIdx.y * PBM;
    const int c0 = blockIdx.x * PBN;
    const int tid = threadIdx.x;
    const int tx = tid & 15;
    const int ty = tid >> 4;

    float acc[8][4];
    #pragma unroll
    for (int i = 0; i < 8; ++i)
        #pragma unroll
        for (int j = 0; j < 4; ++j) acc[i][j] = 0.0f;

    for (int k0 = 0; k0 < kDM; k0 += PBK) {
        #pragma unroll
        for (int r = 0; r < 2; ++r) {
            int f   = tid + r * 256;
            int row = f >> 2;
            int kk  = (f & 3) * 4;
            float4 v = *reinterpret_cast<const float4*>(X + (n0 + row) * kDM + k0 + kk);
            As[kk + 0][row] = v.x; As[kk + 1][row] = v.y;
            As[kk + 2][row] = v.z; As[kk + 3][row] = v.w;
        }
        {
            int n  = tid >> 2;
            int kk = (tid & 3) * 4;
            float4 v = *reinterpret_cast<const float4*>(W + (c0 + n) * kDM + k0 + kk);
            Bs[kk + 0][n] = v.x; Bs[kk + 1][n] = v.y;
            Bs[kk + 2][n] = v.z; Bs[kk + 3][n] = v.w;
        }
        __syncthreads();

        #pragma unroll
        for (int k = 0; k < PBK; ++k) {
            float4 a0 = *reinterpret_cast<const float4*>(&As[k][ty * 8]);
            float4 a1 = *reinterpret_cast<const float4*>(&As[k][ty * 8 + 4]);
            float4 bb = *reinterpret_cast<const float4*>(&Bs[k][tx * 4]);
            float a[8] = {a0.x, a0.y, a0.z, a0.w, a1.x, a1.y, a1.z, a1.w};
            float b[4] = {bb.x, bb.y, bb.z, bb.w};
            #pragma unroll
            for (int i = 0; i < 8; ++i)
                #pragma unroll
                for (int j = 0; j < 4; ++j)
                    acc[i][j] = fmaf(a[i], b[j], acc[i][j]);
        }
        __syncthreads();
    }

    #pragma unroll
    for (int i = 0; i < 8; ++i) {
        const int row = n0 + ty * 8 + i;
        const int bb  = row / kS;
        const int ss  = row % kS;
        #pragma unroll
        for (int j = 0; j < 4; ++j) {
            const int col = c0 + tx * 4 + j;
            const int h = col >> 5, d = col & 31;
            out[((bb * kH + h) * kS + ss) * kDK + d] = acc[i][j] + bias[col];
        }
    }
}

// Full-scan Michelot fallback (exact; used only on candidate overflow)
__device__ __forceinline__ float michelot_full(const float* s, float tau0)
{
    float tau = tau0;
    int prev = -1;
    for (int it = 0; it < 4096; ++it) {
        float sum = 0.0f;
        int cnt = 0;
        #pragma unroll
        for (int i = 0; i < 64; ++i)
            if (s[i] > tau) { sum += s[i]; ++cnt; }
        #pragma unroll
        for (int o = 16; o; o >>= 1) {
            sum += __shfl_xor_sync(0xffffffffu, sum, o);
            cnt += __shfl_xor_sync(0xffffffffu, cnt, o);
        }
        if (cnt == prev || cnt == 0) break;
        tau = (sum - 1.0f) / (float)cnt;
        prev = cnt;
    }
    return tau;
}

// ---------------------------------------------------------------------------
// Fused sparsemax attention, 2 queries/warp, 11 warps (352 thr) per CTA.
// NEW: candidate compaction — only scores > rowmax-1 can be in the support
// (tau_final >= m - 1/k >= m - 1), so Michelot + AV run on a ~20-element
// compacted list in shared instead of scanning 2048 scores per iteration.
// ---------------------------------------------------------------------------
__global__ __launch_bounds__(kThreads, 1)
void attn_kernel(float* __restrict__ out)
{
    __shared__ float4 Ks4[8 * 128];                 // [d4][j], XOR-swizzled (16 KB)
    __shared__ float4 Qs4[kQPerCta * 8];            // 22 queries x 8 float4
    __shared__ float2 Cand[kWarps][2][kCap];        // (value, key-index) lists

    const int bh   = blockIdx.y;
    const int warp = threadIdx.x >> 5;
    const int lane = threadIdx.x & 31;
    const int tid  = threadIdx.x;

    const int q0 = blockIdx.x * kQPerCta;
    int qA = q0 + warp * 2;
    if (qA > kS - 2) qA = kS - 2;          // tail clamp (matches staging)
    const int qB = qA + 1;

    const float* __restrict__ Kbh = g_k + bh * kS * kDK;
    const float* __restrict__ Vbh = g_v + bh * kS * kDK;

    // Stage the CTA's 22 q rows into shared, pair-clamped
    if (tid < kQPerCta * 8) {
        const int ss = tid >> 3, d4 = tid & 7;
        int qr = q0 + (ss & ~1);
        if (qr > kS - 2) qr = kS - 2;
        qr += (ss & 1);
        Qs4[tid] = *reinterpret_cast<const float4*>(
            g_q + (bh * kS + qr) * kDK + d4 * 4);
    }

    float sA[64], sB[64];   // score j = (i>>2)*128 + (i&3)*32 + lane

    #pragma unroll 1
    for (int t = 0; t < 16; ++t) {
        __syncthreads();
        #pragma unroll
        for (int r = 0; r < 3; ++r) {
            int f = tid + r * kThreads;
            if (f < 1024) {
                int j  = f >> 3;
                int d4 = f & 7;
                Ks4[d4 * 128 + (j ^ d4)] =
                    *reinterpret_cast<const float4*>(Kbh + (t * 128 + j) * kDK + d4 * 4);
            }
        }
        __syncthreads();

        float aA[4] = {0.f, 0.f, 0.f, 0.f};
        float aB[4] = {0.f, 0.f, 0.f, 0.f};
        #pragma unroll
        for (int dd = 0; dd < 8; ++dd) {
            const float4 qa = Qs4[(warp * 2 + 0) * 8 + dd];   // broadcast LDS
            const float4 qb = Qs4[(warp * 2 + 1) * 8 + dd];   // broadcast LDS
            #pragma unroll
            for (int k = 0; k < 4; ++k) {
                const float4 kv = Ks4[dd * 128 + ((k * 32 + lane) ^ dd)];
                aA[k] = fmaf(kv.x, qa.x, aA[k]);
                aA[k] = fmaf(kv.y, qa.y, aA[k]);
                aA[k] = fmaf(kv.z, qa.z, aA[k]);
                aA[k] = fmaf(kv.w, qa.w, aA[k]);
                aB[k] = fmaf(kv.x, qb.x, aB[k]);
                aB[k] = fmaf(kv.y, qb.y, aB[k]);
                aB[k] = fmaf(kv.z, qb.z, aB[k]);
                aB[k] = fmaf(kv.w, qb.w, aB[k]);
            }
        }
        #pragma unroll
        for (int k = 0; k < 4; ++k) {
            sA[t * 4 + k] = aA[k] * kScale;
            sB[t * 4 + k] = aB[k] * kScale;
        }
    }

    // Row max (both queries)
    float mA = -FLT_MAX, mB = -FLT_MAX;
    #pragma unroll
    for (int i = 0; i < 64; ++i) { mA = fmaxf(mA, sA[i]); mB = fmaxf(mB, sB[i]); }
    #pragma unroll
    for (int o = 16; o; o >>= 1) {
        mA = fmaxf(mA, __shfl_xor_sync(0xffffffffu, mA, o));
        mB = fmaxf(mB, __shfl_xor_sync(0xffffffffu, mB, o));
    }
    const float thrA = mA - 1.0f;
    const float thrB = mB - 1.0f;

    // Candidate compaction: push (value, key index) of all s > thr to shared.
    float2* __restrict__ cA = Cand[warp][0];
    float2* __restrict__ cB = Cand[warp][1];
    const unsigned lmask = (1u << lane) - 1u;
    int nA = 0, nB = 0;
    #pragma unroll 1
    for (int i = 0; i < 64; ++i) {
        const int jbase = (i >> 2) * 128 + (i & 3) * 32 + lane;
        bool ca = sA[i] > thrA;
        bool cb = sB[i] > thrB;
        unsigned ma = __ballot_sync(0xffffffffu, ca);
        unsigned mb = __ballot_sync(0xffffffffu, cb);
        int pa = __popc(ma), pb = __popc(mb);
        if (ca && nA + pa <= kCap)
            cA[nA + __popc(ma & lmask)] = make_float2(sA[i], __int_as_float(jbase));
        if (cb && nB + pb <= kCap)
            cB[nB + __popc(mb & lmask)] = make_float2(sB[i], __int_as_float(jbase));
        nA += pa; nB += pb;
    }
    const bool ovfA = nA > kCap;
    const bool ovfB = nB > kCap;
    __syncwarp();

    // ---- tau via Michelot on compacted candidates (2 regs/lane) ----
    float tauA, tauB;
    if (!ovfA) {
        float c0 = (lane      < nA) ? cA[lane].x      : -FLT_MAX;
        float c1 = (lane + 32 < nA) ? cA[lane + 32].x : -FLT_MAX;
        float tau = thrA; int prev = -1;
        for (int it = 0; it < 80; ++it) {
            float sum = 0.f; int cnt = 0;
            if (c0 > tau) { sum += c0; ++cnt; }
            if (c1 > tau) { sum += c1; ++cnt; }
            #pragma unroll
            for (int o = 16; o; o >>= 1) {
                sum += __shfl_xor_sync(0xffffffffu, sum, o);
                cnt += __shfl_xor_sync(0xffffffffu, cnt, o);
            }
            if (cnt == prev || cnt == 0) break;
            tau = (sum - 1.0f) / (float)cnt;
            prev = cnt;
        }
        tauA = tau;
    } else {
        tauA = michelot_full(sA, thrA);
    }
    if (!ovfB) {
        float c0 = (lane      < nB) ? cB[lane].x      : -FLT_MAX;
        float c1 = (lane + 32 < nB) ? cB[lane + 32].x : -FLT_MAX;
        float tau = thrB; int prev = -1;
        for (int it = 0; it < 80; ++it) {
            float sum = 0.f; int cnt = 0;
            if (c0 > tau) { sum += c0; ++cnt; }
            if (c1 > tau) { sum += c1; ++cnt; }
            #pragma unroll
            for (int o = 16; o; o >>= 1) {
                sum += __shfl_xor_sync(0xffffffffu, sum, o);
                cnt += __shfl_xor_sync(0xffffffffu, cnt, o);
            }
            if (cnt == prev || cnt == 0) break;
            tau = (sum - 1.0f) / (float)cnt;
            prev = cnt;
        }
        tauB = tau;
    } else {
        tauB = michelot_full(sB, thrB);
    }

    // ---- sparse AV over candidates: warp-uniform, pipelined LDG ----
    float accA = 0.0f, accB = 0.0f;
    if (!ovfA) {
        #pragma unroll 2
        for (int c = 0; c < nA; ++c) {
            float2 p = cA[c];                       // broadcast LDS
            float w = fmaxf(p.x - tauA, 0.0f);
            accA = fmaf(w, __ldg(Vbh + __float_as_int(p.y) * kDK + lane), accA);
        }
    } else {
        #pragma unroll 1
        for (int i = 0; i < 64; ++i) {
            const float wA = sA[i] - tauA;
            unsigned mask = __ballot_sync(0xffffffffu, wA > 0.0f);
            const float* __restrict__ Vb =
                Vbh + ((i >> 2) * 128 + (i & 3) * 32) * kDK + lane;
            while (mask) {
                int b = __ffs(mask) - 1;
                mask &= mask - 1;
                float wb = __shfl_sync(0xffffffffu, wA, b);
                accA = fmaf(wb, __ldg(Vb + b * kDK), accA);
            }
        }
    }
    if (!ovfB) {
        #pragma unroll 2
        for (int c = 0; c < nB; ++c) {
            float2 p = cB[c];                       // broadcast LDS
            float w = fmaxf(p.x - tauB, 0.0f);
            accB = fmaf(w, __ldg(Vbh + __float_as_int(p.y) * kDK + lane), accB);
        }
    } else {
        #pragma unroll 1
        for (int i = 0; i < 64; ++i) {
            const float wB = sB[i] - tauB;
            unsigned mask = __ballot_sync(0xffffffffu, wB > 0.0f);
            const float* __restrict__ Vb =
                Vbh + ((i >> 2) * 128 + (i & 3) * 32) * kDK + lane;
            while (mask) {
                int b = __ffs(mask) - 1;
                mask &= mask - 1;
                float wb = __shfl_sync(0xffffffffu, wB, b);
                accB = fmaf(wb, __ldg(Vb + b * kDK), accB);
            }
        }
    }

    const int bb = bh >> 3;
    const int h  = bh & 7;
    out[(bb * kS + qA) * kDM + h * kDK + lane] = accA;
    out[(bb * kS + qB) * kDM + h * kDK + lane] = accB;
}

// ---------------------------------------------------------------------------
extern "C" void kernel_launch(void* const* d_in, const int* in_sizes, int n_in,
                              void* d_out, int out_size)
{
    const float* query = (const float*)d_in[0];
    const float* key   = (const float*)d_in[1];
    const float* value = (const float*)d_in[2];
    const float* Wq    = (const float*)d_in[3];
    const float* bq    = (const float*)d_in[4];
    const float* Wk    = (const float*)d_in[5];
    const float* bk    = (const float*)d_in[6];
    const float* Wv    = (const float*)d_in[7];
    const float* bv    = (const float*)d_in[8];
    float* out = (float*)d_out;

    dim3 pgrid(kDM / 64, kNRow / 128, 3);      // (4, 32, 3)
    proj_kernel<<<pgrid, 256>>>(query, key, value, Wq, bq, Wk, bk, Wv, bv);

    const int qblocks = (kS + kQPerCta - 1) / kQPerCta;   // 94
    dim3 agrid(qblocks, kB * kH);
    attn_kernel<<<agrid, kThreads>>>(out);

    (void)in_sizes; (void)n_in; (void)out_size;
}